// round 15
// baseline (speedup 1.0000x reference)
#include <cuda_runtime.h>
#include <cuda_fp16.h>
#include <cstdint>

// Problem constants
#define T_STEPS   16
#define BATCH     32
#define CHANS     256
#define HW        256
#define KLAG      4
#define TCTX      12
#define SLICE     (BATCH*CHANS*HW)      // 2,097,152
#define N_SPK     (T_STEPS*SLICE)       // 33,554,432
#define OFF_LOSS  (N_SPK)
#define OFF_LSP   (N_SPK + 1)
#define OFF_LSN   (N_SPK + 1 + TCTX*BATCH)
#define INV_CHW   (1.0f / 65536.0f)
#define CTXW      (SLICE / 32)          // u32 words per t = 65536

// Scratch (device globals)
__device__ uint32_t g_ctxbit[TCTX * CTXW];   // bit-packed binary context
__device__ uint32_t g_spkbit[TCTX * CTXW];   // bit-packed binary spk (t=4..15)
__device__ __half   g_w16[CHANS * CHANS];
__device__ float g_dpos[TCTX * BATCH];
__device__ float g_dneg[TCTX * BATCH];
__device__ int   g_inv[BATCH];

// ---------------------------------------------------------------------------
__global__ void init_kernel(const int* __restrict__ rand_idx) {
    int tid = threadIdx.x;
    if (tid < TCTX * BATCH) { g_dpos[tid] = 0.f; g_dneg[tid] = 0.f; }
    if (tid < BATCH) g_inv[rand_idx[tid]] = tid;
}

// Convert W (fp32) -> fp16 once.
__global__ void convw_kernel(const float* __restrict__ Wm) {
    int i = (blockIdx.x * 256 + threadIdx.x) * 4;
    float4 v = *(const float4*)(Wm + i);
    __half2 h01 = __floats2half2_rn(v.x, v.y);
    __half2 h23 = __floats2half2_rn(v.z, v.w);
    uint2 pk;
    pk.x = *(const uint32_t*)&h01;
    pk.y = *(const uint32_t*)&h23;
    *(uint2*)&g_w16[i] = pk;
}

// ---------------------------------------------------------------------------
// Scan + copy: copy spk_rec -> out; bit-pack spk (t>=4) and scan ctx (t<12)
// via ballot. Bit p of word m = hw position 32m+p.
// ---------------------------------------------------------------------------
__global__ __launch_bounds__(256) void scan_copy_kernel(
    const float* __restrict__ spk, float* __restrict__ out)
{
    const int i4 = blockIdx.x * blockDim.x + threadIdx.x;   // 0 .. SLICE/4-1
    const int lane = threadIdx.x & 31;
    const float4* __restrict__ spk4 = (const float4*)spk;
    float4* __restrict__ out4 = (float4*)out;

    float4 mem = make_float4(0.f, 0.f, 0.f, 0.f);

    #pragma unroll
    for (int t = 0; t < T_STEPS; t++) {
        size_t idx = (size_t)t * (SLICE/4) + i4;
        float4 x = spk4[idx];
        out4[idx] = x;
        if (t >= KLAG) {
            unsigned s0 = __ballot_sync(0xffffffffu, x.x > 0.5f);
            unsigned s1 = __ballot_sync(0xffffffffu, x.y > 0.5f);
            unsigned s2 = __ballot_sync(0xffffffffu, x.z > 0.5f);
            unsigned s3 = __ballot_sync(0xffffffffu, x.w > 0.5f);
            if (lane < 4) {
                unsigned w = 0;
                #pragma unroll
                for (int L = 0; L < 8; L++) {
                    unsigned src = lane * 8 + L;
                    w |= ((s0 >> src) & 1u) << (4 * L + 0);
                    w |= ((s1 >> src) & 1u) << (4 * L + 1);
                    w |= ((s2 >> src) & 1u) << (4 * L + 2);
                    w |= ((s3 >> src) & 1u) << (4 * L + 3);
                }
                g_spkbit[(size_t)(t - KLAG) * CTXW + (size_t)(i4 >> 5) * 4 + lane] = w;
            }
        }
        if (t < TCTX) {
            float r0 = mem.x > 1.f ? 1.f : 0.f;
            float r1 = mem.y > 1.f ? 1.f : 0.f;
            float r2 = mem.z > 1.f ? 1.f : 0.f;
            float r3 = mem.w > 1.f ? 1.f : 0.f;
            mem.x = 0.5f * mem.x + x.x - r0;
            mem.y = 0.5f * mem.y + x.y - r1;
            mem.z = 0.5f * mem.z + x.z - r2;
            mem.w = 0.5f * mem.w + x.w - r3;
            unsigned bq0 = __ballot_sync(0xffffffffu, mem.x > 1.f);
            unsigned bq1 = __ballot_sync(0xffffffffu, mem.y > 1.f);
            unsigned bq2 = __ballot_sync(0xffffffffu, mem.z > 1.f);
            unsigned bq3 = __ballot_sync(0xffffffffu, mem.w > 1.f);
            if (lane < 4) {
                unsigned w = 0;
                #pragma unroll
                for (int L = 0; L < 8; L++) {
                    unsigned src = lane * 8 + L;
                    w |= ((bq0 >> src) & 1u) << (4 * L + 0);
                    w |= ((bq1 >> src) & 1u) << (4 * L + 1);
                    w |= ((bq2 >> src) & 1u) << (4 * L + 2);
                    w |= ((bq3 >> src) & 1u) << (4 * L + 3);
                }
                g_ctxbit[(size_t)t * CTXW + (size_t)(i4 >> 5) * 4 + lane] = w;
            }
        }
    }
}

// ---------------------------------------------------------------------------
// FP16 tensor-core GEMM. A (W) via cp.async 2-stage; B (spk) expanded in-smem
// from packed bits. Block tile 128(o) x 128(hw), K=256 in 4 chunks of 64.
// 8 warps (2x4), warp tile 64x32. Epilogue vs bit-packed ctx.
// ---------------------------------------------------------------------------
#define KC 64
#define NCHUNK 4
#define AS_STRIDE 72    // fp16: 144B/row (proven conflict-free, R5)
#define BS_STRIDE 136   // fp16: 272B/row (proven conflict-free, R5)
#define A_TILE (128 * AS_STRIDE)
#define B_TILE (KC * BS_STRIDE)
#define SMEM_TOTAL ((2 * A_TILE + 2 * B_TILE) * 2)   // bytes = 71680

__device__ __forceinline__ uint32_t smem_u32(const void* p) {
    return (uint32_t)__cvta_generic_to_shared(p);
}
__device__ __forceinline__ void cp16(uint32_t dst, const void* src) {
    asm volatile("cp.async.cg.shared.global [%0], [%1], 16;" :: "r"(dst), "l"(src));
}
__device__ __forceinline__ void cp_commit() {
    asm volatile("cp.async.commit_group;");
}
template<int N> __device__ __forceinline__ void cp_wait() {
    asm volatile("cp.async.wait_group %0;" :: "n"(N));
}
__device__ __forceinline__ void ldsm_x4(uint32_t* r, uint32_t a) {
    asm volatile("ldmatrix.sync.aligned.m8n8.x4.shared.b16 {%0,%1,%2,%3}, [%4];"
        : "=r"(r[0]), "=r"(r[1]), "=r"(r[2]), "=r"(r[3]) : "r"(a));
}
__device__ __forceinline__ void ldsm_x4_t(uint32_t* r, uint32_t a) {
    asm volatile("ldmatrix.sync.aligned.m8n8.x4.trans.shared.b16 {%0,%1,%2,%3}, [%4];"
        : "=r"(r[0]), "=r"(r[1]), "=r"(r[2]), "=r"(r[3]) : "r"(a));
}
__device__ __forceinline__ void mma_fp16(float* c, const uint32_t* a, const uint32_t* b) {
    asm volatile(
        "mma.sync.aligned.m16n8k16.row.col.f32.f16.f16.f32 "
        "{%0,%1,%2,%3}, {%4,%5,%6,%7}, {%8,%9}, {%0,%1,%2,%3};\n"
        : "+f"(c[0]), "+f"(c[1]), "+f"(c[2]), "+f"(c[3])
        : "r"(a[0]), "r"(a[1]), "r"(a[2]), "r"(a[3]), "r"(b[0]), "r"(b[1]));
}
// bits 2e,2e+1 of w -> packed half2 {0|1, 0|1}
__device__ __forceinline__ uint32_t bits2h2(uint32_t w, int b) {
    return ((w >> b) & 1u) * 0x3C00u + ((w >> (b + 1)) & 1u) * 0x3C000000u;
}

__global__ __launch_bounds__(256, 2) void gemm_reduce_kernel()
{
    extern __shared__ __align__(16) __half SM[];
    __half* As0 = SM;                       // [2][128*AS_STRIDE]
    __half* Bs0 = SM + 2 * A_TILE;          // [2][KC*BS_STRIDE]

    const int p  = blockIdx.x;        // 0..383
    const int tt = p >> 5;            // 0..11
    const int bp = p & 31;            // 0..31
    const int q  = blockIdx.y;        // 0..3
    const int o0 = (q >> 1) * 128;
    const int h0 = (q & 1) * 128;

    const int tid  = threadIdx.x;
    const int wid  = tid >> 5;
    const int lane = tid & 31;
    const int gr   = lane >> 2;
    const int qq   = lane & 3;
    const int wm   = (wid & 1) * 64;
    const int wn   = (wid >> 1) * 32;
    const int lrow = lane & 15;
    const int lcol = (lane >> 4) * 8;

    const __half* __restrict__ Wb = g_w16 + (size_t)o0 * CHANS;
    // packed spk words for this (tt,bp), h-half h0: 8 words per channel row
    const uint32_t* __restrict__ Sp =
        g_spkbit + (size_t)tt * CTXW + (size_t)bp * CHANS * 8 + (h0 >> 5);

    // B expansion coords: thread -> (k-row, 32-hw word)
    const int e_k = tid >> 2;            // 0..63
    const int e_w = tid & 3;             // word within 128-hw half

    float acc[4][4][4];
    #pragma unroll
    for (int i = 0; i < 4; i++)
        #pragma unroll
        for (int j = 0; j < 4; j++)
            #pragma unroll
            for (int r = 0; r < 4; r++) acc[i][j][r] = 0.f;

    #define A_FILL(c0_, buf)                                                    \
        do {                                                                    \
            __half* dstA = As0 + (buf) * A_TILE;                                \
            _Pragma("unroll")                                                   \
            for (int ps = 0; ps < 4; ps++) {                                    \
                int id = ps * 256 + tid;                                        \
                int row = id >> 3;                                              \
                int ch  = (id & 7) * 8;                                         \
                cp16(smem_u32(dstA + row * AS_STRIDE + ch),                     \
                     Wb + (size_t)row * CHANS + (c0_) + ch);                    \
            }                                                                   \
            cp_commit();                                                        \
        } while (0)

    #define B_EXPAND(w_, buf)                                                   \
        do {                                                                    \
            __half* dstB = Bs0 + (buf) * B_TILE + e_k * BS_STRIDE + e_w * 32;   \
            _Pragma("unroll")                                                   \
            for (int g2 = 0; g2 < 4; g2++) {                                    \
                uint4 v;                                                        \
                v.x = bits2h2(w_, g2 * 8 + 0);                                  \
                v.y = bits2h2(w_, g2 * 8 + 2);                                  \
                v.z = bits2h2(w_, g2 * 8 + 4);                                  \
                v.w = bits2h2(w_, g2 * 8 + 6);                                  \
                *(uint4*)(dstB + g2 * 8) = v;                                   \
            }                                                                   \
        } while (0)

    // Prologue
    uint32_t w0     = Sp[(size_t)(0 * KC + e_k) * 8 + e_w];
    uint32_t w_hold = Sp[(size_t)(1 * KC + e_k) * 8 + e_w];
    A_FILL(0, 0);
    A_FILL(KC, 1);
    B_EXPAND(w0, 0);

    #pragma unroll
    for (int c = 0; c < NCHUNK; c++) {
        const int buf = c & 1;
        if (c < NCHUNK - 1) {
            A_FILL((c + 1) * KC, (c + 1) & 1);
            cp_wait<1>();
        } else {
            cp_wait<0>();
        }
        __syncthreads();
        if (c < NCHUNK - 1) {
            B_EXPAND(w_hold, (c + 1) & 1);
            if (c < NCHUNK - 2)
                w_hold = Sp[(size_t)((c + 2) * KC + e_k) * 8 + e_w];
        }

        const __half* sA = As0 + buf * A_TILE;
        const __half* sB = Bs0 + buf * B_TILE;
        #pragma unroll
        for (int ks = 0; ks < 4; ks++) {
            const int kb = ks * 16;
            uint32_t af[4][4];
            #pragma unroll
            for (int i = 0; i < 4; i++)
                ldsm_x4(af[i], smem_u32(sA + (wm + i * 16 + lrow) * AS_STRIDE + kb + lcol));
            uint32_t bf[2][4];
            #pragma unroll
            for (int jj = 0; jj < 2; jj++)
                ldsm_x4_t(bf[jj], smem_u32(sB + (kb + lrow) * BS_STRIDE + wn + jj * 16 + lcol));
            #pragma unroll
            for (int i = 0; i < 4; i++)
                #pragma unroll
                for (int j = 0; j < 4; j++)
                    mma_fp16(acc[i][j], af[i], &bf[j >> 1][(j & 1) * 2]);
        }
        __syncthreads();
    }

    // Epilogue: reduce fragments against bit-packed ctx (pos & neg).
    const int bn = g_inv[bp];
    const int widx = (h0 + wn) >> 5;            // 0..7
    const uint32_t* __restrict__ wp_base =
        g_ctxbit + (size_t)tt * CTXW + ((size_t)bp * CHANS + o0) * 8 + widx;
    const uint32_t* __restrict__ wn_base =
        g_ctxbit + (size_t)tt * CTXW + ((size_t)bn * CHANS + o0) * 8 + widx;

    float pp = 0.f, pn = 0.f;
    #pragma unroll
    for (int i = 0; i < 4; i++) {
        const int row0 = wm + i * 16 + gr;
        const int row1 = row0 + 8;
        const uint32_t wp0 = wp_base[(size_t)row0 * 8];
        const uint32_t wp1 = wp_base[(size_t)row1 * 8];
        const uint32_t wn0 = wn_base[(size_t)row0 * 8];
        const uint32_t wn1 = wn_base[(size_t)row1 * 8];
        #pragma unroll
        for (int j = 0; j < 4; j++) {
            const int sh = j * 8 + qq * 2;
            pp += acc[i][j][0] * (float)((wp0 >> sh) & 1u)
                + acc[i][j][1] * (float)((wp0 >> (sh + 1)) & 1u)
                + acc[i][j][2] * (float)((wp1 >> sh) & 1u)
                + acc[i][j][3] * (float)((wp1 >> (sh + 1)) & 1u);
            pn += acc[i][j][0] * (float)((wn0 >> sh) & 1u)
                + acc[i][j][1] * (float)((wn0 >> (sh + 1)) & 1u)
                + acc[i][j][2] * (float)((wn1 >> sh) & 1u)
                + acc[i][j][3] * (float)((wn1 >> (sh + 1)) & 1u);
        }
    }

    #pragma unroll
    for (int off = 16; off > 0; off >>= 1) {
        pp += __shfl_xor_sync(0xffffffffu, pp, off);
        pn += __shfl_xor_sync(0xffffffffu, pn, off);
    }
    if (lane == 0) {
        atomicAdd(&g_dpos[tt * BATCH + bp], pp);
        atomicAdd(&g_dneg[tt * BATCH + bn], pn);
    }
}

// ---------------------------------------------------------------------------
__global__ void finalize_kernel(float* __restrict__ out) {
    __shared__ float shneg[TCTX * BATCH];
    __shared__ float shlsn[TCTX];
    __shared__ float shsum[TCTX * BATCH];
    const int tid = threadIdx.x;   // 0..383

    float lsp = logf(expf(g_dpos[tid] * INV_CHW) + 1e-4f);
    out[OFF_LSP + tid] = lsp;
    shneg[tid] = expf(g_dneg[tid] * INV_CHW) + 1e-4f;
    __syncthreads();

    if (tid < TCTX) {
        float s = 0.f;
        #pragma unroll
        for (int b = 0; b < BATCH; b++) s += shneg[tid * BATCH + b];
        float lsn = logf(s);
        shlsn[tid] = lsn;
        out[OFF_LSN + tid] = lsn;
    }
    __syncthreads();

    shsum[tid] = shlsn[tid >> 5] - lsp;
    __syncthreads();
    if (tid < 128) shsum[tid] = shsum[tid] + shsum[tid + 128] + shsum[tid + 256];
    __syncthreads();
    for (int off = 64; off > 0; off >>= 1) {
        if (tid < off) shsum[tid] += shsum[tid + off];
        __syncthreads();
    }
    if (tid == 0) out[OFF_LOSS] = shsum[0] * (1.0f / (TCTX * BATCH));
}

// ---------------------------------------------------------------------------
extern "C" void kernel_launch(void* const* d_in, const int* in_sizes, int n_in,
                              void* d_out, int out_size) {
    const float* spk  = (const float*)d_in[0];
    const float* Wm   = (const float*)d_in[2];
    const int*   ridx = (const int*)d_in[3];
    float* out = (float*)d_out;

    cudaFuncSetAttribute(gemm_reduce_kernel,
                         cudaFuncAttributeMaxDynamicSharedMemorySize, SMEM_TOTAL);

    init_kernel<<<1, 384>>>(ridx);
    convw_kernel<<<64, 256>>>(Wm);
    scan_copy_kernel<<<SLICE / 4 / 256, 256>>>(spk, out);
    gemm_reduce_kernel<<<dim3(TCTX * BATCH, 4), 256, SMEM_TOTAL>>>();
    finalize_kernel<<<1, 384>>>(out);
}

// round 16
// speedup vs baseline: 1.1296x; 1.1296x over previous
#include <cuda_runtime.h>
#include <cuda_fp16.h>
#include <cstdint>

// Problem constants
#define T_STEPS   16
#define BATCH     32
#define CHANS     256
#define HW        256
#define KLAG      4
#define TCTX      12
#define SLICE     (BATCH*CHANS*HW)      // 2,097,152
#define N_SPK     (T_STEPS*SLICE)       // 33,554,432
#define OFF_LOSS  (N_SPK)
#define OFF_LSP   (N_SPK + 1)
#define OFF_LSN   (N_SPK + 1 + TCTX*BATCH)
#define INV_CHW   (1.0f / 65536.0f)
#define CTXW      (SLICE / 32)          // u32 words per t = 65536
#define GRID_TOTAL (TCTX * BATCH * 4)   // 1536 gemm blocks

// Scratch (device globals)
__device__ uint32_t      g_ctxbit[TCTX * CTXW];          // bit-packed binary context
__device__ __half        g_spk16[(size_t)TCTX * SLICE];  // fp16 spk slices t=4..15
__device__ __half        g_w16[CHANS * CHANS];
__device__ float g_dpos[TCTX * BATCH];
__device__ float g_dneg[TCTX * BATCH];
__device__ int   g_inv[BATCH];
__device__ int   g_counter;

// ---------------------------------------------------------------------------
// Merged init + W conversion. <<<64, 256>>>
// ---------------------------------------------------------------------------
__global__ void initconv_kernel(const float* __restrict__ Wm,
                                const int* __restrict__ rand_idx) {
    int i = (blockIdx.x * 256 + threadIdx.x) * 4;
    float4 v = *(const float4*)(Wm + i);
    __half2 h01 = __floats2half2_rn(v.x, v.y);
    __half2 h23 = __floats2half2_rn(v.z, v.w);
    uint2 pk;
    pk.x = *(const uint32_t*)&h01;
    pk.y = *(const uint32_t*)&h23;
    *(uint2*)&g_w16[i] = pk;

    if (blockIdx.x == 0) {
        for (int k = threadIdx.x; k < TCTX * BATCH; k += 256) {
            g_dpos[k] = 0.f; g_dneg[k] = 0.f;
        }
        if (threadIdx.x < BATCH) g_inv[rand_idx[threadIdx.x]] = threadIdx.x;
        if (threadIdx.x == 0) g_counter = 0;
    }
}

// ---------------------------------------------------------------------------
// Scan + copy: copy spk_rec -> out, leaky scan -> bit-packed ctx (ballot),
// and emit fp16 spk slices for t >= KLAG.
// ---------------------------------------------------------------------------
__global__ __launch_bounds__(256) void scan_copy_kernel(
    const float* __restrict__ spk, float* __restrict__ out)
{
    const int i4 = blockIdx.x * blockDim.x + threadIdx.x;   // 0 .. SLICE/4-1
    const int lane = threadIdx.x & 31;
    const float4* __restrict__ spk4 = (const float4*)spk;
    float4* __restrict__ out4 = (float4*)out;

    float4 mem = make_float4(0.f, 0.f, 0.f, 0.f);

    #pragma unroll
    for (int t = 0; t < T_STEPS; t++) {
        size_t idx = (size_t)t * (SLICE/4) + i4;
        float4 x = spk4[idx];
        out4[idx] = x;
        if (t >= KLAG) {
            __half2 h01 = __floats2half2_rn(x.x, x.y);
            __half2 h23 = __floats2half2_rn(x.z, x.w);
            uint2 pk;
            pk.x = *(const uint32_t*)&h01;
            pk.y = *(const uint32_t*)&h23;
            *(uint2*)&g_spk16[(size_t)(t - KLAG) * SLICE + (size_t)i4 * 4] = pk;
        }
        if (t < TCTX) {
            float r0 = mem.x > 1.f ? 1.f : 0.f;
            float r1 = mem.y > 1.f ? 1.f : 0.f;
            float r2 = mem.z > 1.f ? 1.f : 0.f;
            float r3 = mem.w > 1.f ? 1.f : 0.f;
            mem.x = 0.5f * mem.x + x.x - r0;
            mem.y = 0.5f * mem.y + x.y - r1;
            mem.z = 0.5f * mem.z + x.z - r2;
            mem.w = 0.5f * mem.w + x.w - r3;
            unsigned bq0 = __ballot_sync(0xffffffffu, mem.x > 1.f);
            unsigned bq1 = __ballot_sync(0xffffffffu, mem.y > 1.f);
            unsigned bq2 = __ballot_sync(0xffffffffu, mem.z > 1.f);
            unsigned bq3 = __ballot_sync(0xffffffffu, mem.w > 1.f);
            if (lane < 4) {
                unsigned w = 0;
                #pragma unroll
                for (int L = 0; L < 8; L++) {
                    unsigned src = lane * 8 + L;
                    w |= ((bq0 >> src) & 1u) << (4 * L + 0);
                    w |= ((bq1 >> src) & 1u) << (4 * L + 1);
                    w |= ((bq2 >> src) & 1u) << (4 * L + 2);
                    w |= ((bq3 >> src) & 1u) << (4 * L + 3);
                }
                g_ctxbit[(size_t)t * CTXW + (size_t)(i4 >> 5) * 4 + lane] = w;
            }
        }
    }
}

// ---------------------------------------------------------------------------
// FP16 tensor-core GEMM (m16n8k16 + ldmatrix) with cp.async 2-stage pipeline.
// Block tile 128(o) x 128(hw), K=256 in chunks of 32. 8 warps (2x4),
// warp tile 64x32. Epilogue vs bit-packed ctx (prefetched).
// Last block (completion counter) runs the finalize step.
// ---------------------------------------------------------------------------
#define KC 32
#define AS_STRIDE 40    // fp16: 80B/row = 5 groups -> rows hit 8 distinct groups
#define BS_STRIDE 136   // fp16: 272B/row = 17 groups -> conflict-free

__device__ __forceinline__ uint32_t smem_u32(const void* p) {
    return (uint32_t)__cvta_generic_to_shared(p);
}
__device__ __forceinline__ void cp16(uint32_t dst, const void* src) {
    asm volatile("cp.async.cg.shared.global [%0], [%1], 16;" :: "r"(dst), "l"(src));
}
__device__ __forceinline__ void cp_commit() {
    asm volatile("cp.async.commit_group;");
}
template<int N> __device__ __forceinline__ void cp_wait() {
    asm volatile("cp.async.wait_group %0;" :: "n"(N));
}
__device__ __forceinline__ void ldsm_x4(uint32_t* r, uint32_t a) {
    asm volatile("ldmatrix.sync.aligned.m8n8.x4.shared.b16 {%0,%1,%2,%3}, [%4];"
        : "=r"(r[0]), "=r"(r[1]), "=r"(r[2]), "=r"(r[3]) : "r"(a));
}
__device__ __forceinline__ void ldsm_x4_t(uint32_t* r, uint32_t a) {
    asm volatile("ldmatrix.sync.aligned.m8n8.x4.trans.shared.b16 {%0,%1,%2,%3}, [%4];"
        : "=r"(r[0]), "=r"(r[1]), "=r"(r[2]), "=r"(r[3]) : "r"(a));
}
__device__ __forceinline__ void mma_fp16(float* c, const uint32_t* a, const uint32_t* b) {
    asm volatile(
        "mma.sync.aligned.m16n8k16.row.col.f32.f16.f16.f32 "
        "{%0,%1,%2,%3}, {%4,%5,%6,%7}, {%8,%9}, {%0,%1,%2,%3};\n"
        : "+f"(c[0]), "+f"(c[1]), "+f"(c[2]), "+f"(c[3])
        : "r"(a[0]), "r"(a[1]), "r"(a[2]), "r"(a[3]), "r"(b[0]), "r"(b[1]));
}

__global__ __launch_bounds__(256, 2) void gemm_reduce_kernel(float* __restrict__ out)
{
    const int p  = blockIdx.x;        // 0..383
    const int tt = p >> 5;            // 0..11
    const int bp = p & 31;            // 0..31
    const int q  = blockIdx.y;        // 0..3
    const int o0 = (q >> 1) * 128;
    const int h0 = (q & 1) * 128;

    __shared__ __align__(16) __half As[2][128 * AS_STRIDE]; // [buf][o][k]
    __shared__ __align__(16) __half Bs[2][KC  * BS_STRIDE]; // [buf][k][hw]
    __shared__ int lastflag;

    const int tid  = threadIdx.x;
    const int wid  = tid >> 5;
    const int lane = tid & 31;
    const int gr   = lane >> 2;
    const int qq   = lane & 3;
    const int wm   = (wid & 1) * 64;
    const int wn   = (wid >> 1) * 32;
    const int lrow = lane & 15;
    const int lcol = (lane >> 4) * 8;

    const __half* __restrict__ Sb = g_spk16 + ((size_t)tt * BATCH + bp) * (CHANS * HW);
    const __half* __restrict__ Wb = g_w16 + (size_t)o0 * CHANS;

    // ---- Prefetch epilogue ctx words (pos & neg) ----
    const int bn = g_inv[bp];
    const int widx = (h0 + wn) >> 5;            // 0..7
    const uint32_t* __restrict__ wp_base =
        g_ctxbit + (size_t)tt * CTXW + ((size_t)bp * CHANS + o0) * 8 + widx;
    const uint32_t* __restrict__ wn_base =
        g_ctxbit + (size_t)tt * CTXW + ((size_t)bn * CHANS + o0) * 8 + widx;
    uint32_t wpr[4][2], wnr[4][2];
    #pragma unroll
    for (int i = 0; i < 4; i++) {
        const int row0 = wm + i * 16 + gr;
        wpr[i][0] = wp_base[(size_t)row0 * 8];
        wpr[i][1] = wp_base[(size_t)(row0 + 8) * 8];
        wnr[i][0] = wn_base[(size_t)row0 * 8];
        wnr[i][1] = wn_base[(size_t)(row0 + 8) * 8];
    }

    // Per-thread fill coordinates (2 x 16B for A, 2 x 16B for B per chunk)
    const int a_row0 = tid >> 2;                 // 0..63
    const int a_ch   = (tid & 3) * 8;            // 0,8,16,24
    const int b_row0 = tid >> 4;                 // 0..15
    const int b_ch   = (tid & 15) * 8;           // 0..120

    float acc[4][4][4];
    #pragma unroll
    for (int i = 0; i < 4; i++)
        #pragma unroll
        for (int j = 0; j < 4; j++)
            #pragma unroll
            for (int r = 0; r < 4; r++) acc[i][j][r] = 0.f;

    #define FILL_STAGE(c0, buf)                                                 \
        do {                                                                    \
            cp16(smem_u32(&As[buf][(a_row0      ) * AS_STRIDE + a_ch]),         \
                 Wb + (size_t)(a_row0      ) * CHANS + (c0) + a_ch);            \
            cp16(smem_u32(&As[buf][(a_row0 + 64 ) * AS_STRIDE + a_ch]),         \
                 Wb + (size_t)(a_row0 + 64 ) * CHANS + (c0) + a_ch);            \
            cp16(smem_u32(&Bs[buf][(b_row0      ) * BS_STRIDE + b_ch]),         \
                 Sb + (size_t)((c0) + b_row0      ) * HW + h0 + b_ch);          \
            cp16(smem_u32(&Bs[buf][(b_row0 + 16 ) * BS_STRIDE + b_ch]),         \
                 Sb + (size_t)((c0) + b_row0 + 16 ) * HW + h0 + b_ch);          \
            cp_commit();                                                        \
        } while (0)

    FILL_STAGE(0, 0);

    #pragma unroll
    for (int c = 0; c < 8; c++) {
        const int buf = c & 1;
        if (c < 7) {
            FILL_STAGE((c + 1) * KC, (c + 1) & 1);
            cp_wait<1>();
        } else {
            cp_wait<0>();
        }
        __syncthreads();

        #pragma unroll
        for (int ks = 0; ks < 2; ks++) {
            const int kb = ks * 16;
            uint32_t af[4][4];
            #pragma unroll
            for (int i = 0; i < 4; i++)
                ldsm_x4(af[i], smem_u32(&As[buf][(wm + i * 16 + lrow) * AS_STRIDE + kb + lcol]));
            uint32_t bf[2][4];
            #pragma unroll
            for (int jj = 0; jj < 2; jj++)
                ldsm_x4_t(bf[jj], smem_u32(&Bs[buf][(kb + lrow) * BS_STRIDE + wn + jj * 16 + lcol]));
            #pragma unroll
            for (int i = 0; i < 4; i++)
                #pragma unroll
                for (int j = 0; j < 4; j++)
                    mma_fp16(acc[i][j], af[i], &bf[j >> 1][(j & 1) * 2]);
        }
        __syncthreads();
    }

    // Epilogue: reduce fragments against prefetched bit-packed ctx.
    float pp = 0.f, pn = 0.f;
    #pragma unroll
    for (int i = 0; i < 4; i++) {
        #pragma unroll
        for (int j = 0; j < 4; j++) {
            const int sh = j * 8 + qq * 2;
            pp += acc[i][j][0] * (float)((wpr[i][0] >> sh) & 1u)
                + acc[i][j][1] * (float)((wpr[i][0] >> (sh + 1)) & 1u)
                + acc[i][j][2] * (float)((wpr[i][1] >> sh) & 1u)
                + acc[i][j][3] * (float)((wpr[i][1] >> (sh + 1)) & 1u);
            pn += acc[i][j][0] * (float)((wnr[i][0] >> sh) & 1u)
                + acc[i][j][1] * (float)((wnr[i][0] >> (sh + 1)) & 1u)
                + acc[i][j][2] * (float)((wnr[i][1] >> sh) & 1u)
                + acc[i][j][3] * (float)((wnr[i][1] >> (sh + 1)) & 1u);
        }
    }

    #pragma unroll
    for (int off = 16; off > 0; off >>= 1) {
        pp += __shfl_xor_sync(0xffffffffu, pp, off);
        pn += __shfl_xor_sync(0xffffffffu, pn, off);
    }
    if (lane == 0) {
        atomicAdd(&g_dpos[tt * BATCH + bp], pp);
        atomicAdd(&g_dneg[tt * BATCH + bn], pn);
    }

    // ---- Last-block finalize ----
    __syncthreads();            // block's atomics issued
    __threadfence();            // make them globally visible
    if (tid == 0) {
        int prev = atomicAdd(&g_counter, 1);
        lastflag = (prev == GRID_TOTAL - 1);
    }
    __syncthreads();
    if (!lastflag) return;
    __threadfence();            // acquire: order subsequent reads

    float* shneg = (float*)&As[0][0];   // 384 floats
    float* shlsn = shneg + 384;         // 12 floats (pad to 16)
    float* shsum = shlsn + 16;          // 384 floats

    for (int k = tid; k < TCTX * BATCH; k += 256) {
        float dp = __ldcg(&g_dpos[k]);
        float dn = __ldcg(&g_dneg[k]);
        float lsp = logf(expf(dp * INV_CHW) + 1e-4f);
        out[OFF_LSP + k] = lsp;
        shneg[k] = expf(dn * INV_CHW) + 1e-4f;
        shsum[k] = -lsp;
    }
    __syncthreads();
    if (tid < TCTX) {
        float s = 0.f;
        #pragma unroll
        for (int b = 0; b < BATCH; b++) s += shneg[tid * BATCH + b];
        float lsn = logf(s);
        shlsn[tid] = lsn;
        out[OFF_LSN + tid] = lsn;
    }
    __syncthreads();
    for (int k = tid; k < TCTX * BATCH; k += 256) shsum[k] += shlsn[k >> 5];
    __syncthreads();
    if (tid < 128) shsum[tid] += shsum[tid + 256];
    __syncthreads();
    for (int off = 128; off > 0; off >>= 1) {
        if (tid < off) shsum[tid] += shsum[tid + off];
        __syncthreads();
    }
    if (tid == 0) out[OFF_LOSS] = shsum[0] * (1.0f / (TCTX * BATCH));
}

// ---------------------------------------------------------------------------
extern "C" void kernel_launch(void* const* d_in, const int* in_sizes, int n_in,
                              void* d_out, int out_size) {
    const float* spk  = (const float*)d_in[0];
    const float* Wm   = (const float*)d_in[2];
    const int*   ridx = (const int*)d_in[3];
    float* out = (float*)d_out;

    initconv_kernel<<<64, 256>>>(Wm, ridx);
    scan_copy_kernel<<<SLICE / 4 / 256, 256>>>(spk, out);
    gemm_reduce_kernel<<<dim3(TCTX * BATCH, 4), 256>>>(out);
}